// round 9
// baseline (speedup 1.0000x reference)
#include <cuda_runtime.h>
#include <cstdint>

// Row gather: out[row][:] = table[idx[row]][:], row in [0, 212992), row = 128B.
// Best measured family (R4): 256-thread blocks, 32 rows/warp, 8 independent
// float4 gathers per thread (MLP=8), 832 blocks. This round keeps that shape
// and adds only: per-warp dtype probe (no block barrier) and __stcs streaming
// stores (dead output data must not evict the L2-warm table).
// __ldg for gathers: R8 showed L1 bypass (__ldcg) regresses.

static constexpr int  EMB_DIM        = 32;
static constexpr long NROWS          = 4096L * 26L * 2L;   // 212992
static constexpr int  THREADS        = 256;
static constexpr int  VECS_PER_ROW   = EMB_DIM / 4;        // 8
static constexpr int  ROWS_PER_WARP  = 32;
static constexpr int  WARPS_PER_BLOCK= THREADS / 32;       // 8
static constexpr int  ROWS_PER_BLOCK = WARPS_PER_BLOCK * ROWS_PER_WARP;  // 256
static constexpr int  BLOCKS         = (int)(NROWS / ROWS_PER_BLOCK);    // 832, exact
static constexpr int  STEPS          = 8;                  // 4 rows per step

__global__ __launch_bounds__(THREADS)
void gather_rows_kernel(const void*   __restrict__ idx_raw,
                        const float4* __restrict__ table,
                        float4*       __restrict__ out)
{
    const int lane = threadIdx.x & 31;
    const int warp = threadIdx.x >> 5;

    // ---- per-warp dtype probe: high words of the first 32 8-byte pairs.
    // Same 256B for every warp -> L1-hot after first touch per SM.
    unsigned int hiw = ((const unsigned int*)idx_raw)[2 * lane + 1];
    const bool is32 = __any_sync(0xffffffffu, hiw != 0);

    const long rowBase = ((long)blockIdx.x * WARPS_PER_BLOCK + warp) * ROWS_PER_WARP;

    // ---- one coalesced index load: lane L carries row rowBase+L ----
    long long myIdx;
    if (is32) myIdx = (long long)__ldg(((const int*)idx_raw) + rowBase + lane);
    else      myIdx = __ldg(((const long long*)idx_raw) + rowBase + lane);

    const int subrow = lane >> 3;   // 0..3: row within a 4-row step
    const int col    = lane & 7;    // float4 slot within row

    // ---- distribute indices: step s covers rows rowBase + s*4 .. +3 ----
    long r[STEPS];
#pragma unroll
    for (int s = 0; s < STEPS; s++)
        r[s] = (long)__shfl_sync(0xffffffffu, myIdx, s * 4 + subrow);

    // ---- 8 independent gathers (MLP=8), L1-allowed ----
    float4 v[STEPS];
#pragma unroll
    for (int s = 0; s < STEPS; s++)
        v[s] = __ldg(table + r[s] * VECS_PER_ROW + col);

    // ---- 8 coalesced streaming stores (512B contiguous per warp/step) ----
#pragma unroll
    for (int s = 0; s < STEPS; s++)
        __stcs(out + (rowBase + s * 4 + subrow) * VECS_PER_ROW + col, v[s]);
}

extern "C" void kernel_launch(void* const* d_in, const int* in_sizes, int n_in,
                              void* d_out, int out_size)
{
    // Pick the index tensor by element count (212992 vs 32,000,000).
    const void*  idx;
    const float* table;
    if (in_sizes[0] == (int)NROWS) {
        idx   = d_in[0];
        table = (const float*)d_in[1];
    } else {
        idx   = d_in[1];
        table = (const float*)d_in[0];
    }

    gather_rows_kernel<<<BLOCKS, THREADS>>>(idx, (const float4*)table, (float4*)d_out);
}